// round 7
// baseline (speedup 1.0000x reference)
#include <cuda_runtime.h>
#include <cstdint>
#include <cstddef>

#define BATCH 64
#define DIM 512
#define MAT (DIM * DIM)
#define NUM_ITER 5
#define BK 32
#define NSTAGE (DIM / BK)      // 16
#define PSTRIDE 36             // float2 per smem row (32 + 4 pad): conflict-free
#define NBUF 3

// ---------------- device scratch: all matrices as (hi,lo) float2 ----------------
__device__ float2 g_Y[2][(size_t)BATCH * MAT];
__device__ float2 g_Z[2][(size_t)BATCH * MAT];
__device__ float2 g_T[(size_t)BATCH * MAT];
__device__ float g_norm[BATCH];

// upper-triangular tile pairs for 4x4 grid of 128-wide tiles
__constant__ int c_ti[10] = {0, 0, 0, 0, 1, 1, 1, 2, 2, 3};
__constant__ int c_tj[10] = {0, 1, 2, 3, 1, 2, 3, 2, 3, 3};

#define PLANE_F2 (128 * PSTRIDE)          // 4608 float2
#define STAGE_F2 (2 * PLANE_F2)           // 9216 float2 (A plane + B plane)
#define SMEM_BYTES (NBUF * STAGE_F2 * 8)  // 221184 bytes

// ---------------- helpers ----------------
__device__ __forceinline__ uint32_t smem_u32(const void* p) {
    uint32_t a;
    asm("{ .reg .u64 t; cvta.to.shared.u64 t, %1; cvt.u32.u64 %0, t; }" : "=r"(a) : "l"(p));
    return a;
}
__device__ __forceinline__ void cp16(uint32_t dst, const void* src) {
    asm volatile("cp.async.cg.shared.global [%0], [%1], 16;" :: "r"(dst), "l"(src));
}
__device__ __forceinline__ float2 split2f(float v) {
    uint32_t h, l;
    asm("cvt.rna.tf32.f32 %0, %1;" : "=r"(h) : "f"(v));
    float hf = __uint_as_float(h);
    asm("cvt.rna.tf32.f32 %0, %1;" : "=r"(l) : "f"(v - hf));
    return make_float2(__uint_as_float(h), __uint_as_float(l));
}
__device__ __forceinline__ void mma8(float* c, uint32_t a0, uint32_t a1, uint32_t a2,
                                     uint32_t a3, uint32_t b0, uint32_t b1) {
    asm volatile(
        "mma.sync.aligned.m16n8k8.row.col.f32.tf32.tf32.f32 "
        "{%0,%1,%2,%3}, {%4,%5,%6,%7}, {%8,%9}, {%0,%1,%2,%3};"
        : "+f"(c[0]), "+f"(c[1]), "+f"(c[2]), "+f"(c[3])
        : "r"(a0), "r"(a1), "r"(a2), "r"(a3), "r"(b0), "r"(b1));
}

// ---------------- Frobenius norm per batch ----------------
__global__ void norm_kernel(const float* __restrict__ x) {
    const int b = blockIdx.x;
    const float4* xb = (const float4*)(x + (size_t)b * MAT);
    float s = 0.f;
    for (int i = threadIdx.x; i < MAT / 4; i += blockDim.x) {
        float4 v = xb[i];
        s += v.x * v.x + v.y * v.y + v.z * v.z + v.w * v.w;
    }
    __shared__ float red[8];
    #pragma unroll
    for (int o = 16; o; o >>= 1) s += __shfl_xor_sync(0xFFFFFFFFu, s, o);
    if ((threadIdx.x & 31) == 0) red[threadIdx.x >> 5] = s;
    __syncthreads();
    if (threadIdx.x < 32) {
        s = (threadIdx.x < (int)(blockDim.x >> 5)) ? red[threadIdx.x] : 0.f;
        #pragma unroll
        for (int o = 16; o; o >>= 1) s += __shfl_xor_sync(0xFFFFFFFFu, s, o);
        if (threadIdx.x == 0) g_norm[b] = sqrtf(s);
    }
}

// ---------------- Y0 = split(x / normA) ----------------
__global__ void init_kernel(const float* __restrict__ x, float2* __restrict__ Y0) {
    const int i = blockIdx.x * blockDim.x + threadIdx.x;
    if (i >= BATCH * MAT / 4) return;
    const int b = i / (MAT / 4);
    const float inv = 1.0f / g_norm[b];
    float4 v = ((const float4*)x)[i];
    float2 p0 = split2f(v.x * inv), p1 = split2f(v.y * inv);
    float2 p2 = split2f(v.z * inv), p3 = split2f(v.w * inv);
    ((float4*)Y0)[2 * i]     = make_float4(p0.x, p0.y, p1.x, p1.y);
    ((float4*)Y0)[2 * i + 1] = make_float4(p2.x, p2.y, p3.x, p3.y);
}

// ---------------- Z1 = T0 = split(1.5 I - 0.5 * Y0) ----------------
__global__ void zt_kernel(const float2* __restrict__ Y0, float2* __restrict__ Z1) {
    const int i = blockIdx.x * blockDim.x + threadIdx.x;   // pair of elements
    if (i >= BATCH * MAT / 2) return;
    float4 y = ((const float4*)Y0)[i];
    const int e0 = (2 * i) % MAT;
    const int row = e0 / DIM, col = e0 % DIM;
    float v0 = -0.5f * (y.x + y.y) + ((row == col)     ? 1.5f : 0.0f);
    float v1 = -0.5f * (y.z + y.w) + ((row == col + 1) ? 1.5f : 0.0f);
    float2 p0 = split2f(v0), p1 = split2f(v1);
    ((float4*)Z1)[i] = make_float4(p0.x, p0.y, p1.x, p1.y);
}

// ---------------- out = (hi + lo) * sqrt(normA) ----------------
__global__ void final_kernel(const float2* __restrict__ Y, float* __restrict__ out) {
    const int i = blockIdx.x * blockDim.x + threadIdx.x;   // pair of elements
    if (i >= BATCH * MAT / 2) return;
    const int b = i / (MAT / 2);
    const float s = sqrtf(g_norm[b]);
    float4 y = ((const float4*)Y)[i];
    ((float2*)out)[i] = make_float2((y.x + y.y) * s, (y.z + y.w) * s);
}

// ---------------- 3xTF32 mma.sync symmetric-output batched GEMM ----------------
// Operands pre-split: each element is float2 (tf32 hi, tf32 lo).
// C = A @ B (MODE 0) or 1.5 I - 0.5 A @ B (MODE 1); all matrices symmetric, so
// B fragments read from B[n][k] and only tiles ti<=tj computed (mirror-stored).
// CTA 128x128, 256 threads (warp tile 64x32), BK=32, 3-stage cp.async ring.
// MMA issue order: 3 passes (hh, hl, lh) of 16 INDEPENDENT mmas each, so
// same-accumulator reuse is 16 mmas apart (HMMA RAW latency fully hidden).
template <int MODE>
__global__ void __launch_bounds__(256, 1) gemm_tc(const float2* __restrict__ Ag,
                                                  const float2* __restrict__ Bg,
                                                  float2* __restrict__ Cg) {
    extern __shared__ float2 sm[];
    const int b = blockIdx.z;
    const int ti = c_ti[blockIdx.x];
    const int tj = c_tj[blockIdx.x];
    const int bm = ti * 128;
    const int bn = tj * 128;
    const float2* A = Ag + (size_t)b * MAT;
    const float2* B = Bg + (size_t)b * MAT;
    float2*       C = Cg + (size_t)b * MAT;

    const int tid = threadIdx.x;
    const int wid = tid >> 5;
    const int lane = tid & 31;
    const int gid = lane >> 2;   // 0..7
    const int tig = lane & 3;    // 0..3
    const int wm = wid >> 2;     // 0..1
    const int wn = wid & 3;      // 0..3

    const uint32_t s_base = smem_u32(sm);

    // fill: per stage, A plane + B plane (B rows are B[n][*] via symmetry).
    const int f_row = tid >> 4;            // base row 0..15 (+16 per j)
    const int f_c2 = (tid & 15) * 2;       // float2 col within 32
    const uint32_t f_dst = (uint32_t)(f_row * PSTRIDE + f_c2) * 8;
    auto fill = [&](int buf, int kc) {
        const uint32_t base = s_base + (uint32_t)buf * (STAGE_F2 * 8);
        const int koff = kc * BK;
        const float2* aS = A + (size_t)(bm + f_row) * DIM + koff + f_c2;
        const float2* bS = B + (size_t)(bn + f_row) * DIM + koff + f_c2;
        #pragma unroll
        for (int j = 0; j < 8; ++j) {
            cp16(base + f_dst + (uint32_t)j * 16 * PSTRIDE * 8, aS + (size_t)j * 16 * DIM);
            cp16(base + (uint32_t)PLANE_F2 * 8 + f_dst + (uint32_t)j * 16 * PSTRIDE * 8,
                 bS + (size_t)j * 16 * DIM);
        }
        asm volatile("cp.async.commit_group;" ::: "memory");
    };

    float acc[4][4][4];
    #pragma unroll
    for (int mf = 0; mf < 4; ++mf)
        #pragma unroll
        for (int nf = 0; nf < 4; ++nf)
            #pragma unroll
            for (int e = 0; e < 4; ++e) acc[mf][nf][e] = 0.f;

    fill(0, 0);
    fill(1, 1);

    for (int s = 0; s < NSTAGE; ++s) {
        if (s < NSTAGE - 1) asm volatile("cp.async.wait_group 1;" ::: "memory");
        else                asm volatile("cp.async.wait_group 0;" ::: "memory");
        __syncthreads();   // stage s visible; all warps done with stage s-1

        if (s + 2 < NSTAGE) fill((s + 2) % NBUF, s + 2);  // overwrites stage s-1 buf: safe

        const uint2* pA = (const uint2*)(sm + (s % NBUF) * STAGE_F2);
        const uint2* pB = pA + PLANE_F2;

        #pragma unroll
        for (int k8 = 0; k8 < BK / 8; ++k8) {
            const int kb = k8 * 8 + tig;
            // load ALL fragments for this k8 (hi/lo packed in uint2)
            uint2 Bf[4][2];
            #pragma unroll
            for (int nf = 0; nf < 4; ++nf) {
                const int r = (wn * 32 + nf * 8 + gid) * PSTRIDE;
                Bf[nf][0] = pB[r + kb];
                Bf[nf][1] = pB[r + kb + 4];
            }
            uint2 Af[4][4];
            #pragma unroll
            for (int mf = 0; mf < 4; ++mf) {
                const int r0 = (wm * 64 + mf * 16 + gid) * PSTRIDE;
                const int r1 = r0 + 8 * PSTRIDE;
                Af[mf][0] = pA[r0 + kb];
                Af[mf][1] = pA[r1 + kb];
                Af[mf][2] = pA[r0 + kb + 4];
                Af[mf][3] = pA[r1 + kb + 4];
            }
            // pass 1: hi*hi — 16 independent mmas
            #pragma unroll
            for (int mf = 0; mf < 4; ++mf)
                #pragma unroll
                for (int nf = 0; nf < 4; ++nf)
                    mma8(acc[mf][nf], Af[mf][0].x, Af[mf][1].x, Af[mf][2].x, Af[mf][3].x,
                         Bf[nf][0].x, Bf[nf][1].x);
            // pass 2: hi*lo
            #pragma unroll
            for (int mf = 0; mf < 4; ++mf)
                #pragma unroll
                for (int nf = 0; nf < 4; ++nf)
                    mma8(acc[mf][nf], Af[mf][0].x, Af[mf][1].x, Af[mf][2].x, Af[mf][3].x,
                         Bf[nf][0].y, Bf[nf][1].y);
            // pass 3: lo*hi
            #pragma unroll
            for (int mf = 0; mf < 4; ++mf)
                #pragma unroll
                for (int nf = 0; nf < 4; ++nf)
                    mma8(acc[mf][nf], Af[mf][0].y, Af[mf][1].y, Af[mf][2].y, Af[mf][3].y,
                         Bf[nf][0].x, Bf[nf][1].x);
        }
    }

    // ---------------- epilogue: split result, main + mirror stores ----------------
    #pragma unroll
    for (int mf = 0; mf < 4; ++mf) {
        #pragma unroll
        for (int nf = 0; nf < 4; ++nf) {
            float* cr = acc[mf][nf];
            const int r0 = bm + wm * 64 + mf * 16 + gid;
            const int r1 = r0 + 8;
            const int cb = bn + wn * 32 + nf * 8 + 2 * tig;
            if (MODE == 1) {
                cr[0] = fmaf(cr[0], -0.5f, (cb == r0)     ? 1.5f : 0.0f);
                cr[1] = fmaf(cr[1], -0.5f, (cb + 1 == r0) ? 1.5f : 0.0f);
                cr[2] = fmaf(cr[2], -0.5f, (cb == r1)     ? 1.5f : 0.0f);
                cr[3] = fmaf(cr[3], -0.5f, (cb + 1 == r1) ? 1.5f : 0.0f);
            }
            float2 p0 = split2f(cr[0]), p1 = split2f(cr[1]);
            float2 p2 = split2f(cr[2]), p3 = split2f(cr[3]);
            *(float4*)(C + (size_t)r0 * DIM + cb) = make_float4(p0.x, p0.y, p1.x, p1.y);
            *(float4*)(C + (size_t)r1 * DIM + cb) = make_float4(p2.x, p2.y, p3.x, p3.y);
            if (ti != tj) {  // mirror transposed
                C[(size_t)cb * DIM + r0]       = p0;
                C[(size_t)(cb + 1) * DIM + r0] = p1;
                C[(size_t)cb * DIM + r1]       = p2;
                C[(size_t)(cb + 1) * DIM + r1] = p3;
            }
        }
    }
}

// ---------------- host launcher ----------------
extern "C" void kernel_launch(void* const* d_in, const int* in_sizes, int n_in,
                              void* d_out, int out_size) {
    const float* x = (const float*)d_in[0];
    float* out = (float*)d_out;

    float2 *Yb, *Zb, *Tb;
    cudaGetSymbolAddress((void**)&Yb, g_Y);
    cudaGetSymbolAddress((void**)&Zb, g_Z);
    cudaGetSymbolAddress((void**)&Tb, g_T);
    const size_t half = (size_t)BATCH * MAT;
    float2* Y[2] = {Yb, Yb + half};
    float2* Z[2] = {Zb, Zb + half};

    cudaFuncSetAttribute(gemm_tc<0>, cudaFuncAttributeMaxDynamicSharedMemorySize, SMEM_BYTES);
    cudaFuncSetAttribute(gemm_tc<1>, cudaFuncAttributeMaxDynamicSharedMemorySize, SMEM_BYTES);

    norm_kernel<<<BATCH, 256>>>(x);
    const int total4 = BATCH * MAT / 4;
    const int total2 = BATCH * MAT / 2;
    init_kernel<<<(total4 + 255) / 256, 256>>>(x, Y[0]);

    // iter 0 (Z0 = I): T0 = 1.5I - 0.5*Y0 stored as Z[0]; Y1 = Y0 @ T0
    zt_kernel<<<(total2 + 255) / 256, 256>>>(Y[0], Z[0]);

    dim3 ggrid(10, 1, BATCH);
    gemm_tc<0><<<ggrid, 256, SMEM_BYTES>>>(Y[0], Z[0], Y[1]);
    int ycur = 1, zcur = 0;

    for (int it = 1; it < NUM_ITER; ++it) {
        gemm_tc<1><<<ggrid, 256, SMEM_BYTES>>>(Z[zcur], Y[ycur], Tb);
        gemm_tc<0><<<ggrid, 256, SMEM_BYTES>>>(Y[ycur], Tb, Y[1 - ycur]);
        ycur ^= 1;
        if (it < NUM_ITER - 1) {
            gemm_tc<0><<<ggrid, 256, SMEM_BYTES>>>(Tb, Z[zcur], Z[1 - zcur]);
            zcur ^= 1;
        }
    }

    final_kernel<<<(total2 + 255) / 256, 256>>>(Y[ycur], out);
}

// round 8
// speedup vs baseline: 2.1920x; 2.1920x over previous
#include <cuda_runtime.h>
#include <cstdint>
#include <cstddef>

#define BATCH 64
#define DIM 512
#define MAT (DIM * DIM)
#define NUM_ITER 5
#define BK 32
#define NSTAGE (DIM / BK)   // 16
#define FSTRIDE 36          // f32 plane row stride (floats)
#define HSTRIDE 20          // bf16 plane row stride (u32 = bf16x2 pairs)

// ---------------- device scratch (plain fp32 matrices) ----------------
__device__ float g_Y[2][(size_t)BATCH * MAT];
__device__ float g_Z[2][(size_t)BATCH * MAT];
__device__ float g_T[(size_t)BATCH * MAT];
__device__ float g_norm[BATCH];

// upper-triangular tile pairs for 4x4 grid of 128-wide tiles
__constant__ int c_ti[10] = {0, 0, 0, 0, 1, 1, 1, 2, 2, 3};
__constant__ int c_tj[10] = {0, 1, 2, 3, 1, 2, 3, 2, 3, 3};

// smem float offsets
#define OFF_RAWA 0                               // 2 stages x 128x32 f32
#define OFF_RAWB 8192                            // 2 stages x 128x32 f32
#define OFF_AH   16384                           // 128 x 36 f32 (tf32 hi)
#define OFF_BH   (OFF_AH + 128 * FSTRIDE)
#define OFF_ABH  (OFF_BH + 128 * FSTRIDE)        // u32 planes (bf16x2): A hi
#define OFF_ALB  (OFF_ABH + 128 * HSTRIDE)       // A lo
#define OFF_BBH  (OFF_ALB + 128 * HSTRIDE)       // B hi
#define OFF_BLB  (OFF_BBH + 128 * HSTRIDE)       // B lo
#define SMEM_FLOATS (OFF_BLB + 128 * HSTRIDE)
#define SMEM_BYTES (SMEM_FLOATS * 4)             // 143360

// ---------------- helpers ----------------
__device__ __forceinline__ uint32_t smem_u32(const void* p) {
    uint32_t a;
    asm("{ .reg .u64 t; cvta.to.shared.u64 t, %1; cvt.u32.u64 %0, t; }" : "=r"(a) : "l"(p));
    return a;
}
__device__ __forceinline__ void cp16(uint32_t dst, const void* src) {
    asm volatile("cp.async.cg.shared.global [%0], [%1], 16;" :: "r"(dst), "l"(src));
}
__device__ __forceinline__ void split2(float v, uint32_t& hi, float& lo) {
    asm("cvt.rna.tf32.f32 %0, %1;" : "=r"(hi) : "f"(v));
    lo = v - __uint_as_float(hi);
}
// pack: lo_elem -> bits[15:0] (k even), hi_elem -> bits[31:16] (k odd)
__device__ __forceinline__ uint32_t bfpack(float e_even, float e_odd) {
    uint32_t r;
    asm("cvt.rn.bf16x2.f32 %0, %1, %2;" : "=r"(r) : "f"(e_odd), "f"(e_even));
    return r;
}
__device__ __forceinline__ void mma_tf32(float* c, uint32_t a0, uint32_t a1, uint32_t a2,
                                         uint32_t a3, uint32_t b0, uint32_t b1) {
    asm volatile(
        "mma.sync.aligned.m16n8k8.row.col.f32.tf32.tf32.f32 "
        "{%0,%1,%2,%3}, {%4,%5,%6,%7}, {%8,%9}, {%0,%1,%2,%3};"
        : "+f"(c[0]), "+f"(c[1]), "+f"(c[2]), "+f"(c[3])
        : "r"(a0), "r"(a1), "r"(a2), "r"(a3), "r"(b0), "r"(b1));
}
__device__ __forceinline__ void mma_bf16(float* c, uint32_t a0, uint32_t a1, uint32_t a2,
                                         uint32_t a3, uint32_t b0, uint32_t b1) {
    asm volatile(
        "mma.sync.aligned.m16n8k16.row.col.f32.bf16.bf16.f32 "
        "{%0,%1,%2,%3}, {%4,%5,%6,%7}, {%8,%9}, {%0,%1,%2,%3};"
        : "+f"(c[0]), "+f"(c[1]), "+f"(c[2]), "+f"(c[3])
        : "r"(a0), "r"(a1), "r"(a2), "r"(a3), "r"(b0), "r"(b1));
}

// ---------------- Frobenius norm per batch ----------------
__global__ void norm_kernel(const float* __restrict__ x) {
    const int b = blockIdx.x;
    const float4* xb = (const float4*)(x + (size_t)b * MAT);
    float s = 0.f;
    for (int i = threadIdx.x; i < MAT / 4; i += blockDim.x) {
        float4 v = xb[i];
        s += v.x * v.x + v.y * v.y + v.z * v.z + v.w * v.w;
    }
    __shared__ float red[8];
    #pragma unroll
    for (int o = 16; o; o >>= 1) s += __shfl_xor_sync(0xFFFFFFFFu, s, o);
    if ((threadIdx.x & 31) == 0) red[threadIdx.x >> 5] = s;
    __syncthreads();
    if (threadIdx.x < 32) {
        s = (threadIdx.x < (int)(blockDim.x >> 5)) ? red[threadIdx.x] : 0.f;
        #pragma unroll
        for (int o = 16; o; o >>= 1) s += __shfl_xor_sync(0xFFFFFFFFu, s, o);
        if (threadIdx.x == 0) g_norm[b] = sqrtf(s);
    }
}

// ---------------- Y0 = x / normA ----------------
__global__ void init_kernel(const float* __restrict__ x, float* __restrict__ Y0) {
    const int i = blockIdx.x * blockDim.x + threadIdx.x;
    if (i >= BATCH * MAT / 4) return;
    const int b = i / (MAT / 4);
    const float inv = 1.0f / g_norm[b];
    float4 v = ((const float4*)x)[i];
    v.x *= inv; v.y *= inv; v.z *= inv; v.w *= inv;
    ((float4*)Y0)[i] = v;
}

// ---------------- Z1 = T0 = 1.5 I - 0.5 * Y0 ----------------
__global__ void zt_kernel(const float* __restrict__ Y0, float* __restrict__ Z1) {
    const int i = blockIdx.x * blockDim.x + threadIdx.x;
    if (i >= BATCH * MAT / 4) return;
    float4 v = ((const float4*)Y0)[i];
    const int r = i % (MAT / 4);
    const int row = r / (DIM / 4);
    const int c4 = r % (DIM / 4);
    float4 o;
    o.x = -0.5f * v.x; o.y = -0.5f * v.y; o.z = -0.5f * v.z; o.w = -0.5f * v.w;
    if (c4 == (row >> 2)) ((float*)&o)[row & 3] += 1.5f;
    ((float4*)Z1)[i] = o;
}

// ---------------- out = Y * sqrt(normA) ----------------
__global__ void final_kernel(const float* __restrict__ Y, float* __restrict__ out) {
    const int i = blockIdx.x * blockDim.x + threadIdx.x;
    if (i >= BATCH * MAT / 4) return;
    const int b = i / (MAT / 4);
    const float s = sqrtf(g_norm[b]);
    float4 v = ((const float4*)Y)[i];
    v.x *= s; v.y *= s; v.z *= s; v.w *= s;
    ((float4*)out)[i] = v;
}

// ---------------- hybrid tf32+bf16 symmetric-output batched GEMM ----------------
// C = A@B exact-ish: hi*hi in tf32 (m16n8k8), corrections hi*lo + lo*hi in bf16
// (m16n8k16, half the instructions). All matrices symmetric: B read as B[n][k],
// tiles ti<=tj only (mirror-stored). CTA 128x128, 256 thr, warp tile 64x32,
// BK=32, 2-stage cp.async raw fp32, in-kernel split into hi(f32)/bf16 planes.
template <int MODE>
__global__ void __launch_bounds__(256, 1) gemm_tc(const float* __restrict__ Ag,
                                                  const float* __restrict__ Bg,
                                                  float* __restrict__ Cg) {
    extern __shared__ float sm[];
    const int b = blockIdx.z;
    const int ti = c_ti[blockIdx.x];
    const int tj = c_tj[blockIdx.x];
    const int bm = ti * 128;
    const int bn = tj * 128;
    const float* A = Ag + (size_t)b * MAT;
    const float* B = Bg + (size_t)b * MAT;
    float*       C = Cg + (size_t)b * MAT;

    const int tid = threadIdx.x;
    const int wid = tid >> 5;
    const int lane = tid & 31;
    const int gid = lane >> 2;   // 0..7
    const int tig = lane & 3;    // 0..3
    const int wm = wid >> 2;     // 0..1
    const int wn = wid & 3;      // 0..3

    const uint32_t s_rawA = smem_u32(sm + OFF_RAWA);
    const uint32_t s_rawB = smem_u32(sm + OFF_RAWB);

    auto fill = [&](int stage, int kc) {
        const uint32_t da = s_rawA + (stage & 1) * 4096 * 4;
        const uint32_t db = s_rawB + (stage & 1) * 4096 * 4;
        const size_t koff = (size_t)kc * BK;
        #pragma unroll
        for (int j = 0; j < 4; ++j) {
            const int ch = tid + 256 * j;        // 0..1023
            const int row = ch >> 3;
            const int c8 = (ch & 7) * 4;
            cp16(da + (row * 32 + c8) * 4, A + (size_t)(bm + row) * DIM + koff + c8);
            cp16(db + (row * 32 + c8) * 4, B + (size_t)(bn + row) * DIM + koff + c8);
        }
        asm volatile("cp.async.commit_group;" ::: "memory");
    };

    fill(0, 0);

    float acc[4][4][4];
    #pragma unroll
    for (int mf = 0; mf < 4; ++mf)
        #pragma unroll
        for (int nf = 0; nf < 4; ++nf)
            #pragma unroll
            for (int e = 0; e < 4; ++e) acc[mf][nf][e] = 0.f;

    for (int s = 0; s < NSTAGE; ++s) {
        if (s + 1 < NSTAGE) {
            fill(s + 1, s + 1);
            asm volatile("cp.async.wait_group 1;" ::: "memory");
        } else {
            asm volatile("cp.async.wait_group 0;" ::: "memory");
        }
        __syncthreads();

        // split pass: raw fp32 -> tf32-hi f32 planes + bf16 hi/lo packed planes
        {
            const float* ra = sm + OFF_RAWA + (s & 1) * 4096;
            const float* rb = sm + OFF_RAWB + (s & 1) * 4096;
            uint32_t* abh = (uint32_t*)(sm + OFF_ABH);
            uint32_t* alb = (uint32_t*)(sm + OFF_ALB);
            uint32_t* bbh = (uint32_t*)(sm + OFF_BBH);
            uint32_t* blb = (uint32_t*)(sm + OFF_BLB);
            #pragma unroll
            for (int j = 0; j < 4; ++j) {
                const int f = tid + 256 * j;    // float4 id 0..1023
                const int row = f >> 3;
                const int c4 = (f & 7) * 4;
                const int pidx = row * HSTRIDE + (f & 7) * 2;
                float4 va = *(const float4*)(ra + row * 32 + c4);
                float4 vb = *(const float4*)(rb + row * 32 + c4);
                uint4 h; float4 l;
                split2(va.x, h.x, l.x); split2(va.y, h.y, l.y);
                split2(va.z, h.z, l.z); split2(va.w, h.w, l.w);
                *(uint4*)(sm + OFF_AH + row * FSTRIDE + c4) = h;
                *(uint2*)(abh + pidx) = make_uint2(
                    bfpack(__uint_as_float(h.x), __uint_as_float(h.y)),
                    bfpack(__uint_as_float(h.z), __uint_as_float(h.w)));
                *(uint2*)(alb + pidx) = make_uint2(bfpack(l.x, l.y), bfpack(l.z, l.w));
                split2(vb.x, h.x, l.x); split2(vb.y, h.y, l.y);
                split2(vb.z, h.z, l.z); split2(vb.w, h.w, l.w);
                *(uint4*)(sm + OFF_BH + row * FSTRIDE + c4) = h;
                *(uint2*)(bbh + pidx) = make_uint2(
                    bfpack(__uint_as_float(h.x), __uint_as_float(h.y)),
                    bfpack(__uint_as_float(h.z), __uint_as_float(h.w)));
                *(uint2*)(blb + pidx) = make_uint2(bfpack(l.x, l.y), bfpack(l.z, l.w));
            }
        }
        __syncthreads();

        const uint32_t* ah = (const uint32_t*)(sm + OFF_AH);
        const uint32_t* bh = (const uint32_t*)(sm + OFF_BH);

        // ---- hi*hi in tf32: 4 k8 steps, 16 independent mmas each ----
        #pragma unroll
        for (int k8 = 0; k8 < 4; ++k8) {
            const int kb = k8 * 8 + tig;
            uint32_t Bf[4][2];
            #pragma unroll
            for (int nf = 0; nf < 4; ++nf) {
                const int r = (wn * 32 + nf * 8 + gid) * FSTRIDE;
                Bf[nf][0] = bh[r + kb];
                Bf[nf][1] = bh[r + kb + 4];
            }
            uint32_t Af[4][4];
            #pragma unroll
            for (int mf = 0; mf < 4; ++mf) {
                const int r0 = (wm * 64 + mf * 16 + gid) * FSTRIDE;
                const int r1 = r0 + 8 * FSTRIDE;
                Af[mf][0] = ah[r0 + kb];
                Af[mf][1] = ah[r1 + kb];
                Af[mf][2] = ah[r0 + kb + 4];
                Af[mf][3] = ah[r1 + kb + 4];
            }
            #pragma unroll
            for (int mf = 0; mf < 4; ++mf)
                #pragma unroll
                for (int nf = 0; nf < 4; ++nf)
                    mma_tf32(acc[mf][nf], Af[mf][0], Af[mf][1], Af[mf][2], Af[mf][3],
                             Bf[nf][0], Bf[nf][1]);
        }

        // ---- corrections in bf16 (m16n8k16): 2 slabs, 2 passes of 16 mmas ----
        const uint32_t* abh = (const uint32_t*)(sm + OFF_ABH);
        const uint32_t* alb = (const uint32_t*)(sm + OFF_ALB);
        const uint32_t* bbh = (const uint32_t*)(sm + OFF_BBH);
        const uint32_t* blb = (const uint32_t*)(sm + OFF_BLB);
        #pragma unroll
        for (int slab = 0; slab < 2; ++slab) {
            const int pb = slab * 8 + tig;
            uint32_t Blf[4][2], Bhf[4][2];
            #pragma unroll
            for (int nf = 0; nf < 4; ++nf) {
                const int r = (wn * 32 + nf * 8 + gid) * HSTRIDE;
                Blf[nf][0] = blb[r + pb]; Blf[nf][1] = blb[r + pb + 4];
                Bhf[nf][0] = bbh[r + pb]; Bhf[nf][1] = bbh[r + pb + 4];
            }
            uint32_t Ahf[4][4], Alf[4][4];
            #pragma unroll
            for (int mf = 0; mf < 4; ++mf) {
                const int r0 = (wm * 64 + mf * 16 + gid) * HSTRIDE;
                const int r1 = r0 + 8 * HSTRIDE;
                Ahf[mf][0] = abh[r0 + pb]; Ahf[mf][1] = abh[r1 + pb];
                Ahf[mf][2] = abh[r0 + pb + 4]; Ahf[mf][3] = abh[r1 + pb + 4];
                Alf[mf][0] = alb[r0 + pb]; Alf[mf][1] = alb[r1 + pb];
                Alf[mf][2] = alb[r0 + pb + 4]; Alf[mf][3] = alb[r1 + pb + 4];
            }
            #pragma unroll
            for (int mf = 0; mf < 4; ++mf)
                #pragma unroll
                for (int nf = 0; nf < 4; ++nf)
                    mma_bf16(acc[mf][nf], Ahf[mf][0], Ahf[mf][1], Ahf[mf][2], Ahf[mf][3],
                             Blf[nf][0], Blf[nf][1]);
            #pragma unroll
            for (int mf = 0; mf < 4; ++mf)
                #pragma unroll
                for (int nf = 0; nf < 4; ++nf)
                    mma_bf16(acc[mf][nf], Alf[mf][0], Alf[mf][1], Alf[mf][2], Alf[mf][3],
                             Bhf[nf][0], Bhf[nf][1]);
        }
    }

    // ---------------- epilogue ----------------
    #pragma unroll
    for (int mf = 0; mf < 4; ++mf) {
        #pragma unroll
        for (int nf = 0; nf < 4; ++nf) {
            float* cr = acc[mf][nf];
            const int r0 = bm + wm * 64 + mf * 16 + gid;
            const int r1 = r0 + 8;
            const int cb = bn + wn * 32 + nf * 8 + 2 * tig;
            if (MODE == 1) {
                cr[0] = fmaf(cr[0], -0.5f, (cb == r0)     ? 1.5f : 0.0f);
                cr[1] = fmaf(cr[1], -0.5f, (cb + 1 == r0) ? 1.5f : 0.0f);
                cr[2] = fmaf(cr[2], -0.5f, (cb == r1)     ? 1.5f : 0.0f);
                cr[3] = fmaf(cr[3], -0.5f, (cb + 1 == r1) ? 1.5f : 0.0f);
            }
            *(float2*)(C + (size_t)r0 * DIM + cb) = make_float2(cr[0], cr[1]);
            *(float2*)(C + (size_t)r1 * DIM + cb) = make_float2(cr[2], cr[3]);
            if (ti != tj) {  // mirror transposed
                C[(size_t)cb * DIM + r0]       = cr[0];
                C[(size_t)(cb + 1) * DIM + r0] = cr[1];
                C[(size_t)cb * DIM + r1]       = cr[2];
                C[(size_t)(cb + 1) * DIM + r1] = cr[3];
            }
        }
    }
}

// ---------------- host launcher ----------------
extern "C" void kernel_launch(void* const* d_in, const int* in_sizes, int n_in,
                              void* d_out, int out_size) {
    const float* x = (const float*)d_in[0];
    float* out = (float*)d_out;

    float *Yb, *Zb, *Tb;
    cudaGetSymbolAddress((void**)&Yb, g_Y);
    cudaGetSymbolAddress((void**)&Zb, g_Z);
    cudaGetSymbolAddress((void**)&Tb, g_T);
    const size_t half = (size_t)BATCH * MAT;
    float* Y[2] = {Yb, Yb + half};
    float* Z[2] = {Zb, Zb + half};

    cudaFuncSetAttribute(gemm_tc<0>, cudaFuncAttributeMaxDynamicSharedMemorySize, SMEM_BYTES);
    cudaFuncSetAttribute(gemm_tc<1>, cudaFuncAttributeMaxDynamicSharedMemorySize, SMEM_BYTES);

    norm_kernel<<<BATCH, 256>>>(x);
    const int total4 = BATCH * MAT / 4;
    init_kernel<<<(total4 + 255) / 256, 256>>>(x, Y[0]);

    // iter 0 (Z0 = I): T0 = 1.5I - 0.5*Y0 stored as Z[0]; Y1 = Y0 @ T0
    zt_kernel<<<(total4 + 255) / 256, 256>>>(Y[0], Z[0]);

    dim3 ggrid(10, 1, BATCH);
    gemm_tc<0><<<ggrid, 256, SMEM_BYTES>>>(Y[0], Z[0], Y[1]);
    int ycur = 1, zcur = 0;

    for (int it = 1; it < NUM_ITER; ++it) {
        gemm_tc<1><<<ggrid, 256, SMEM_BYTES>>>(Z[zcur], Y[ycur], Tb);
        gemm_tc<0><<<ggrid, 256, SMEM_BYTES>>>(Y[ycur], Tb, Y[1 - ycur]);
        ycur ^= 1;
        if (it < NUM_ITER - 1) {
            gemm_tc<0><<<ggrid, 256, SMEM_BYTES>>>(Tb, Z[zcur], Z[1 - zcur]);
            zcur ^= 1;
        }
    }

    final_kernel<<<(total4 + 255) / 256, 256>>>(Y[ycur], out);
}

// round 9
// speedup vs baseline: 2.4467x; 1.1162x over previous
#include <cuda_runtime.h>
#include <cstdint>
#include <cstddef>

#define BATCH 64
#define DIM 512
#define MAT (DIM * DIM)
#define NUM_ITER 5
#define BK 32
#define NSTAGE (DIM / BK)   // 16
#define FSTRIDE 36          // f32 plane row stride (floats)
#define HSTRIDE 20          // bf16 plane row stride (u32 = bf16x2 pairs)

// ---------------- device scratch (plain fp32 matrices) ----------------
__device__ float g_Y[2][(size_t)BATCH * MAT];
__device__ float g_Z[2][(size_t)BATCH * MAT];
__device__ float g_T[(size_t)BATCH * MAT];
__device__ float g_norm[BATCH];

// upper-triangular tile pairs for 4x4 grid of 128-wide tiles
__constant__ int c_ti[10] = {0, 0, 0, 0, 1, 1, 1, 2, 2, 3};
__constant__ int c_tj[10] = {0, 1, 2, 3, 1, 2, 3, 2, 3, 3};

// smem float offsets — SINGLE buffered (fits 2 CTAs/SM)
#define OFF_RAWA 0                               // 128x32 f32
#define OFF_RAWB 4096                            // 128x32 f32
#define OFF_AH   8192                            // 128 x 36 f32 (tf32 hi)
#define OFF_BH   (OFF_AH + 128 * FSTRIDE)
#define OFF_ABH  (OFF_BH + 128 * FSTRIDE)        // u32 planes (bf16x2): A hi
#define OFF_ALB  (OFF_ABH + 128 * HSTRIDE)       // A lo
#define OFF_BBH  (OFF_ALB + 128 * HSTRIDE)       // B hi
#define OFF_BLB  (OFF_BBH + 128 * HSTRIDE)       // B lo
#define SMEM_FLOATS (OFF_BLB + 128 * HSTRIDE)
#define SMEM_BYTES (SMEM_FLOATS * 4)             // 110592

// ---------------- helpers ----------------
__device__ __forceinline__ uint32_t smem_u32(const void* p) {
    uint32_t a;
    asm("{ .reg .u64 t; cvta.to.shared.u64 t, %1; cvt.u32.u64 %0, t; }" : "=r"(a) : "l"(p));
    return a;
}
__device__ __forceinline__ void cp16(uint32_t dst, const void* src) {
    asm volatile("cp.async.cg.shared.global [%0], [%1], 16;" :: "r"(dst), "l"(src));
}
__device__ __forceinline__ void split2(float v, uint32_t& hi, float& lo) {
    asm("cvt.rna.tf32.f32 %0, %1;" : "=r"(hi) : "f"(v));
    lo = v - __uint_as_float(hi);
}
// pack: e_even -> bits[15:0], e_odd -> bits[31:16]
__device__ __forceinline__ uint32_t bfpack(float e_even, float e_odd) {
    uint32_t r;
    asm("cvt.rn.bf16x2.f32 %0, %1, %2;" : "=r"(r) : "f"(e_odd), "f"(e_even));
    return r;
}
__device__ __forceinline__ void mma_tf32(float* c, uint32_t a0, uint32_t a1, uint32_t a2,
                                         uint32_t a3, uint32_t b0, uint32_t b1) {
    asm volatile(
        "mma.sync.aligned.m16n8k8.row.col.f32.tf32.tf32.f32 "
        "{%0,%1,%2,%3}, {%4,%5,%6,%7}, {%8,%9}, {%0,%1,%2,%3};"
        : "+f"(c[0]), "+f"(c[1]), "+f"(c[2]), "+f"(c[3])
        : "r"(a0), "r"(a1), "r"(a2), "r"(a3), "r"(b0), "r"(b1));
}
__device__ __forceinline__ void mma_bf16(float* c, uint32_t a0, uint32_t a1, uint32_t a2,
                                         uint32_t a3, uint32_t b0, uint32_t b1) {
    asm volatile(
        "mma.sync.aligned.m16n8k16.row.col.f32.bf16.bf16.f32 "
        "{%0,%1,%2,%3}, {%4,%5,%6,%7}, {%8,%9}, {%0,%1,%2,%3};"
        : "+f"(c[0]), "+f"(c[1]), "+f"(c[2]), "+f"(c[3])
        : "r"(a0), "r"(a1), "r"(a2), "r"(a3), "r"(b0), "r"(b1));
}

// ---------------- Frobenius norm per batch ----------------
__global__ void norm_kernel(const float* __restrict__ x) {
    const int b = blockIdx.x;
    const float4* xb = (const float4*)(x + (size_t)b * MAT);
    float s = 0.f;
    for (int i = threadIdx.x; i < MAT / 4; i += blockDim.x) {
        float4 v = xb[i];
        s += v.x * v.x + v.y * v.y + v.z * v.z + v.w * v.w;
    }
    __shared__ float red[8];
    #pragma unroll
    for (int o = 16; o; o >>= 1) s += __shfl_xor_sync(0xFFFFFFFFu, s, o);
    if ((threadIdx.x & 31) == 0) red[threadIdx.x >> 5] = s;
    __syncthreads();
    if (threadIdx.x < 32) {
        s = (threadIdx.x < (int)(blockDim.x >> 5)) ? red[threadIdx.x] : 0.f;
        #pragma unroll
        for (int o = 16; o; o >>= 1) s += __shfl_xor_sync(0xFFFFFFFFu, s, o);
        if (threadIdx.x == 0) g_norm[b] = sqrtf(s);
    }
}

// ---------------- Y0 = x / normA ----------------
__global__ void init_kernel(const float* __restrict__ x, float* __restrict__ Y0) {
    const int i = blockIdx.x * blockDim.x + threadIdx.x;
    if (i >= BATCH * MAT / 4) return;
    const int b = i / (MAT / 4);
    const float inv = 1.0f / g_norm[b];
    float4 v = ((const float4*)x)[i];
    v.x *= inv; v.y *= inv; v.z *= inv; v.w *= inv;
    ((float4*)Y0)[i] = v;
}

// ---------------- Z1 = T0 = 1.5 I - 0.5 * Y0 ----------------
__global__ void zt_kernel(const float* __restrict__ Y0, float* __restrict__ Z1) {
    const int i = blockIdx.x * blockDim.x + threadIdx.x;
    if (i >= BATCH * MAT / 4) return;
    float4 v = ((const float4*)Y0)[i];
    const int r = i % (MAT / 4);
    const int row = r / (DIM / 4);
    const int c4 = r % (DIM / 4);
    float4 o;
    o.x = -0.5f * v.x; o.y = -0.5f * v.y; o.z = -0.5f * v.z; o.w = -0.5f * v.w;
    if (c4 == (row >> 2)) ((float*)&o)[row & 3] += 1.5f;
    ((float4*)Z1)[i] = o;
}

// ---------------- out = Y * sqrt(normA) ----------------
__global__ void final_kernel(const float* __restrict__ Y, float* __restrict__ out) {
    const int i = blockIdx.x * blockDim.x + threadIdx.x;
    if (i >= BATCH * MAT / 4) return;
    const int b = i / (MAT / 4);
    const float s = sqrtf(g_norm[b]);
    float4 v = ((const float4*)Y)[i];
    v.x *= s; v.y *= s; v.z *= s; v.w *= s;
    ((float4*)out)[i] = v;
}

// ---------------- hybrid tf32+bf16 symmetric-output batched GEMM ----------------
// hi*hi in tf32 (m16n8k8), corrections hi*lo + lo*hi in bf16 (m16n8k16).
// All matrices symmetric: B read as B[n][k], tiles ti<=tj only, mirror-stored.
// CTA 128x128, 256 thr, warp tile 64x32, BK=32. SINGLE-buffered smem (108 KB)
// -> 2 CTAs/SM; next-stage cp.async issued before the MMA phase so it overlaps.
template <int MODE>
__global__ void __launch_bounds__(256, 2) gemm_tc(const float* __restrict__ Ag,
                                                  const float* __restrict__ Bg,
                                                  float* __restrict__ Cg) {
    extern __shared__ float sm[];
    const int b = blockIdx.z;
    const int ti = c_ti[blockIdx.x];
    const int tj = c_tj[blockIdx.x];
    const int bm = ti * 128;
    const int bn = tj * 128;
    const float* A = Ag + (size_t)b * MAT;
    const float* B = Bg + (size_t)b * MAT;
    float*       C = Cg + (size_t)b * MAT;

    const int tid = threadIdx.x;
    const int wid = tid >> 5;
    const int lane = tid & 31;
    const int gid = lane >> 2;   // 0..7
    const int tig = lane & 3;    // 0..3
    const int wm = wid >> 2;     // 0..1
    const int wn = wid & 3;      // 0..3

    const uint32_t s_rawA = smem_u32(sm + OFF_RAWA);
    const uint32_t s_rawB = smem_u32(sm + OFF_RAWB);

    auto fill = [&](int kc) {
        const size_t koff = (size_t)kc * BK;
        #pragma unroll
        for (int j = 0; j < 4; ++j) {
            const int ch = tid + 256 * j;        // 0..1023
            const int row = ch >> 3;
            const int c8 = (ch & 7) * 4;
            cp16(s_rawA + (row * 32 + c8) * 4, A + (size_t)(bm + row) * DIM + koff + c8);
            cp16(s_rawB + (row * 32 + c8) * 4, B + (size_t)(bn + row) * DIM + koff + c8);
        }
        asm volatile("cp.async.commit_group;" ::: "memory");
    };

    float acc[4][4][4];
    #pragma unroll
    for (int mf = 0; mf < 4; ++mf)
        #pragma unroll
        for (int nf = 0; nf < 4; ++nf)
            #pragma unroll
            for (int e = 0; e < 4; ++e) acc[mf][nf][e] = 0.f;

    fill(0);
    asm volatile("cp.async.wait_group 0;" ::: "memory");
    __syncthreads();

    for (int s = 0; s < NSTAGE; ++s) {
        // ---- split pass: raw fp32 -> tf32-hi f32 planes + bf16 hi/lo planes ----
        {
            uint32_t* abh = (uint32_t*)(sm + OFF_ABH);
            uint32_t* alb = (uint32_t*)(sm + OFF_ALB);
            uint32_t* bbh = (uint32_t*)(sm + OFF_BBH);
            uint32_t* blb = (uint32_t*)(sm + OFF_BLB);
            #pragma unroll
            for (int j = 0; j < 4; ++j) {
                const int f = tid + 256 * j;    // float4 id 0..1023
                const int row = f >> 3;
                const int c4 = (f & 7) * 4;
                const int pidx = row * HSTRIDE + (f & 7) * 2;
                float4 va = *(const float4*)(sm + OFF_RAWA + row * 32 + c4);
                float4 vb = *(const float4*)(sm + OFF_RAWB + row * 32 + c4);
                uint4 h; float4 l;
                split2(va.x, h.x, l.x); split2(va.y, h.y, l.y);
                split2(va.z, h.z, l.z); split2(va.w, h.w, l.w);
                *(uint4*)(sm + OFF_AH + row * FSTRIDE + c4) = h;
                *(uint2*)(abh + pidx) = make_uint2(
                    bfpack(__uint_as_float(h.x), __uint_as_float(h.y)),
                    bfpack(__uint_as_float(h.z), __uint_as_float(h.w)));
                *(uint2*)(alb + pidx) = make_uint2(bfpack(l.x, l.y), bfpack(l.z, l.w));
                split2(vb.x, h.x, l.x); split2(vb.y, h.y, l.y);
                split2(vb.z, h.z, l.z); split2(vb.w, h.w, l.w);
                *(uint4*)(sm + OFF_BH + row * FSTRIDE + c4) = h;
                *(uint2*)(bbh + pidx) = make_uint2(
                    bfpack(__uint_as_float(h.x), __uint_as_float(h.y)),
                    bfpack(__uint_as_float(h.z), __uint_as_float(h.w)));
                *(uint2*)(blb + pidx) = make_uint2(bfpack(l.x, l.y), bfpack(l.z, l.w));
            }
        }
        __syncthreads();   // planes ready; raw buffer free

        // issue next stage's loads now — they overlap the MMA phase below
        if (s + 1 < NSTAGE) fill(s + 1);

        const uint32_t* ah = (const uint32_t*)(sm + OFF_AH);
        const uint32_t* bh = (const uint32_t*)(sm + OFF_BH);

        // ---- hi*hi in tf32: 4 k8 steps ----
        #pragma unroll
        for (int k8 = 0; k8 < 4; ++k8) {
            const int kb = k8 * 8 + tig;
            uint32_t Bf[4][2];
            #pragma unroll
            for (int nf = 0; nf < 4; ++nf) {
                const int r = (wn * 32 + nf * 8 + gid) * FSTRIDE;
                Bf[nf][0] = bh[r + kb];
                Bf[nf][1] = bh[r + kb + 4];
            }
            #pragma unroll
            for (int mf = 0; mf < 4; ++mf) {
                const int r0 = (wm * 64 + mf * 16 + gid) * FSTRIDE;
                const int r1 = r0 + 8 * FSTRIDE;
                uint32_t a0 = ah[r0 + kb], a1 = ah[r1 + kb];
                uint32_t a2 = ah[r0 + kb + 4], a3 = ah[r1 + kb + 4];
                #pragma unroll
                for (int nf = 0; nf < 4; ++nf)
                    mma_tf32(acc[mf][nf], a0, a1, a2, a3, Bf[nf][0], Bf[nf][1]);
            }
        }

        // ---- corrections in bf16 (m16n8k16): 2 slabs ----
        const uint32_t* abh = (const uint32_t*)(sm + OFF_ABH);
        const uint32_t* alb = (const uint32_t*)(sm + OFF_ALB);
        const uint32_t* bbh = (const uint32_t*)(sm + OFF_BBH);
        const uint32_t* blb = (const uint32_t*)(sm + OFF_BLB);
        #pragma unroll
        for (int slab = 0; slab < 2; ++slab) {
            const int pb = slab * 8 + tig;
            uint32_t Blf[4][2], Bhf[4][2];
            #pragma unroll
            for (int nf = 0; nf < 4; ++nf) {
                const int r = (wn * 32 + nf * 8 + gid) * HSTRIDE;
                Blf[nf][0] = blb[r + pb]; Blf[nf][1] = blb[r + pb + 4];
                Bhf[nf][0] = bbh[r + pb]; Bhf[nf][1] = bbh[r + pb + 4];
            }
            #pragma unroll
            for (int mf = 0; mf < 4; ++mf) {
                const int r0 = (wm * 64 + mf * 16 + gid) * HSTRIDE;
                const int r1 = r0 + 8 * HSTRIDE;
                uint32_t h0 = abh[r0 + pb], h1 = abh[r1 + pb];
                uint32_t h2 = abh[r0 + pb + 4], h3 = abh[r1 + pb + 4];
                uint32_t l0 = alb[r0 + pb], l1 = alb[r1 + pb];
                uint32_t l2 = alb[r0 + pb + 4], l3 = alb[r1 + pb + 4];
                #pragma unroll
                for (int nf = 0; nf < 4; ++nf)
                    mma_bf16(acc[mf][nf], h0, h1, h2, h3, Blf[nf][0], Blf[nf][1]);
                #pragma unroll
                for (int nf = 0; nf < 4; ++nf)
                    mma_bf16(acc[mf][nf], l0, l1, l2, l3, Bhf[nf][0], Bhf[nf][1]);
            }
        }

        if (s + 1 < NSTAGE) asm volatile("cp.async.wait_group 0;" ::: "memory");
        __syncthreads();   // raw(s+1) ready; planes free for next split
    }

    // ---------------- epilogue ----------------
    #pragma unroll
    for (int mf = 0; mf < 4; ++mf) {
        #pragma unroll
        for (int nf = 0; nf < 4; ++nf) {
            float* cr = acc[mf][nf];
            const int r0 = bm + wm * 64 + mf * 16 + gid;
            const int r1 = r0 + 8;
            const int cb = bn + wn * 32 + nf * 8 + 2 * tig;
            if (MODE == 1) {
                cr[0] = fmaf(cr[0], -0.5f, (cb == r0)     ? 1.5f : 0.0f);
                cr[1] = fmaf(cr[1], -0.5f, (cb + 1 == r0) ? 1.5f : 0.0f);
                cr[2] = fmaf(cr[2], -0.5f, (cb == r1)     ? 1.5f : 0.0f);
                cr[3] = fmaf(cr[3], -0.5f, (cb + 1 == r1) ? 1.5f : 0.0f);
            }
            *(float2*)(C + (size_t)r0 * DIM + cb) = make_float2(cr[0], cr[1]);
            *(float2*)(C + (size_t)r1 * DIM + cb) = make_float2(cr[2], cr[3]);
            if (ti != tj) {  // mirror transposed
                C[(size_t)cb * DIM + r0]       = cr[0];
                C[(size_t)(cb + 1) * DIM + r0] = cr[1];
                C[(size_t)cb * DIM + r1]       = cr[2];
                C[(size_t)(cb + 1) * DIM + r1] = cr[3];
            }
        }
    }
}

// ---------------- host launcher ----------------
extern "C" void kernel_launch(void* const* d_in, const int* in_sizes, int n_in,
                              void* d_out, int out_size) {
    const float* x = (const float*)d_in[0];
    float* out = (float*)d_out;

    float *Yb, *Zb, *Tb;
    cudaGetSymbolAddress((void**)&Yb, g_Y);
    cudaGetSymbolAddress((void**)&Zb, g_Z);
    cudaGetSymbolAddress((void**)&Tb, g_T);
    const size_t half = (size_t)BATCH * MAT;
    float* Y[2] = {Yb, Yb + half};
    float* Z[2] = {Zb, Zb + half};

    cudaFuncSetAttribute(gemm_tc<0>, cudaFuncAttributeMaxDynamicSharedMemorySize, SMEM_BYTES);
    cudaFuncSetAttribute(gemm_tc<1>, cudaFuncAttributeMaxDynamicSharedMemorySize, SMEM_BYTES);

    norm_kernel<<<BATCH, 256>>>(x);
    const int total4 = BATCH * MAT / 4;
    init_kernel<<<(total4 + 255) / 256, 256>>>(x, Y[0]);

    // iter 0 (Z0 = I): T0 = 1.5I - 0.5*Y0 stored as Z[0]; Y1 = Y0 @ T0
    zt_kernel<<<(total4 + 255) / 256, 256>>>(Y[0], Z[0]);

    dim3 ggrid(10, 1, BATCH);
    gemm_tc<0><<<ggrid, 256, SMEM_BYTES>>>(Y[0], Z[0], Y[1]);
    int ycur = 1, zcur = 0;

    for (int it = 1; it < NUM_ITER; ++it) {
        gemm_tc<1><<<ggrid, 256, SMEM_BYTES>>>(Z[zcur], Y[ycur], Tb);
        gemm_tc<0><<<ggrid, 256, SMEM_BYTES>>>(Y[ycur], Tb, Y[1 - ycur]);
        ycur ^= 1;
        if (it < NUM_ITER - 1) {
            gemm_tc<0><<<ggrid, 256, SMEM_BYTES>>>(Tb, Z[zcur], Z[1 - zcur]);
            zcur ^= 1;
        }
    }

    final_kernel<<<(total4 + 255) / 256, 256>>>(Y[ycur], out);
}

// round 10
// speedup vs baseline: 3.3689x; 1.3769x over previous
#include <cuda_runtime.h>
#include <cstdint>
#include <cstddef>

#define BATCH 64
#define DIM 512
#define MAT (DIM * DIM)
#define NUM_ITER 5
#define BK 32
#define NSTAGE (DIM / BK)   // 16
#define HSTRIDE 20          // bf16 plane row stride (u32 = bf16x2 pairs)

// ---------------- device scratch (plain fp32 matrices) ----------------
__device__ float g_Y[2][(size_t)BATCH * MAT];
__device__ float g_Z[2][(size_t)BATCH * MAT];
__device__ float g_T[(size_t)BATCH * MAT];
__device__ float g_norm[BATCH];

// upper-triangular tile pairs for 4x4 grid of 128-wide tiles
__constant__ int c_ti[10] = {0, 0, 0, 0, 1, 1, 1, 2, 2, 3};
__constant__ int c_tj[10] = {0, 1, 2, 3, 1, 2, 3, 2, 3, 3};

// smem u32/float offsets — single buffered, bf16 planes only
#define OFF_RAWA 0                              // 128x32 f32
#define OFF_RAWB 4096                           // 128x32 f32
#define OFF_ABH  8192                           // u32 planes (bf16x2): A hi
#define OFF_ALB  (OFF_ABH + 128 * HSTRIDE)      // A lo
#define OFF_BBH  (OFF_ALB + 128 * HSTRIDE)      // B hi
#define OFF_BLB  (OFF_BBH + 128 * HSTRIDE)      // B lo
#define SMEM_FLOATS (OFF_BLB + 128 * HSTRIDE)   // 18432
#define SMEM_BYTES (SMEM_FLOATS * 4)            // 73728

// ---------------- helpers ----------------
__device__ __forceinline__ uint32_t smem_u32(const void* p) {
    uint32_t a;
    asm("{ .reg .u64 t; cvta.to.shared.u64 t, %1; cvt.u32.u64 %0, t; }" : "=r"(a) : "l"(p));
    return a;
}
__device__ __forceinline__ void cp16(uint32_t dst, const void* src) {
    asm volatile("cp.async.cg.shared.global [%0], [%1], 16;" :: "r"(dst), "l"(src));
}
// pack: e_even -> bits[15:0], e_odd -> bits[31:16]
__device__ __forceinline__ uint32_t bfpack(float e_even, float e_odd) {
    uint32_t r;
    asm("cvt.rn.bf16x2.f32 %0, %1, %2;" : "=r"(r) : "f"(e_odd), "f"(e_even));
    return r;
}
__device__ __forceinline__ void mma_bf16(float* c, uint32_t a0, uint32_t a1, uint32_t a2,
                                         uint32_t a3, uint32_t b0, uint32_t b1) {
    asm volatile(
        "mma.sync.aligned.m16n8k16.row.col.f32.bf16.bf16.f32 "
        "{%0,%1,%2,%3}, {%4,%5,%6,%7}, {%8,%9}, {%0,%1,%2,%3};"
        : "+f"(c[0]), "+f"(c[1]), "+f"(c[2]), "+f"(c[3])
        : "r"(a0), "r"(a1), "r"(a2), "r"(a3), "r"(b0), "r"(b1));
}

// ---------------- Frobenius norm per batch ----------------
__global__ void norm_kernel(const float* __restrict__ x) {
    const int b = blockIdx.x;
    const float4* xb = (const float4*)(x + (size_t)b * MAT);
    float s = 0.f;
    for (int i = threadIdx.x; i < MAT / 4; i += blockDim.x) {
        float4 v = xb[i];
        s += v.x * v.x + v.y * v.y + v.z * v.z + v.w * v.w;
    }
    __shared__ float red[8];
    #pragma unroll
    for (int o = 16; o; o >>= 1) s += __shfl_xor_sync(0xFFFFFFFFu, s, o);
    if ((threadIdx.x & 31) == 0) red[threadIdx.x >> 5] = s;
    __syncthreads();
    if (threadIdx.x < 32) {
        s = (threadIdx.x < (int)(blockDim.x >> 5)) ? red[threadIdx.x] : 0.f;
        #pragma unroll
        for (int o = 16; o; o >>= 1) s += __shfl_xor_sync(0xFFFFFFFFu, s, o);
        if (threadIdx.x == 0) g_norm[b] = sqrtf(s);
    }
}

// ---------------- Y0 = x / normA ----------------
__global__ void init_kernel(const float* __restrict__ x, float* __restrict__ Y0) {
    const int i = blockIdx.x * blockDim.x + threadIdx.x;
    if (i >= BATCH * MAT / 4) return;
    const int b = i / (MAT / 4);
    const float inv = 1.0f / g_norm[b];
    float4 v = ((const float4*)x)[i];
    v.x *= inv; v.y *= inv; v.z *= inv; v.w *= inv;
    ((float4*)Y0)[i] = v;
}

// ---------------- Z1 = T0 = 1.5 I - 0.5 * Y0 ----------------
__global__ void zt_kernel(const float* __restrict__ Y0, float* __restrict__ Z1) {
    const int i = blockIdx.x * blockDim.x + threadIdx.x;
    if (i >= BATCH * MAT / 4) return;
    float4 v = ((const float4*)Y0)[i];
    const int r = i % (MAT / 4);
    const int row = r / (DIM / 4);
    const int c4 = r % (DIM / 4);
    float4 o;
    o.x = -0.5f * v.x; o.y = -0.5f * v.y; o.z = -0.5f * v.z; o.w = -0.5f * v.w;
    if (c4 == (row >> 2)) ((float*)&o)[row & 3] += 1.5f;
    ((float4*)Z1)[i] = o;
}

// ---------------- out = Y * sqrt(normA) ----------------
__global__ void final_kernel(const float* __restrict__ Y, float* __restrict__ out) {
    const int i = blockIdx.x * blockDim.x + threadIdx.x;
    if (i >= BATCH * MAT / 4) return;
    const int b = i / (MAT / 4);
    const float s = sqrtf(g_norm[b]);
    float4 v = ((const float4*)Y)[i];
    v.x *= s; v.y *= s; v.z *= s; v.w *= s;
    ((float4*)out)[i] = v;
}

// ---------------- all-bf16 3-term symmetric-output batched GEMM body ----------------
// C = A@B via hi*hi + hi*lo + lo*hi, hi = bf16(v), lo = bf16(v - hi); all terms
// m16n8k16 bf16 MMA with fp32 accumulate (ll term ~2^-16 dropped).
// All matrices symmetric: B read as B[n][k], tiles ti<=tj only, mirror-stored.
// CTA 128x128, 256 thr, warp tile 64x32, BK=32, single-buffered (72 KB, 2 CTAs/SM);
// next stage's cp.async issued before the MMA phase so it overlaps.
template <int MODE>
__device__ __forceinline__ void gemm_body(const float* __restrict__ A,
                                          const float* __restrict__ B,
                                          float* __restrict__ C,
                                          int ti, int tj, float* sm) {
    const int bm = ti * 128;
    const int bn = tj * 128;
    const int tid = threadIdx.x;
    const int wid = tid >> 5;
    const int lane = tid & 31;
    const int gid = lane >> 2;   // 0..7
    const int tig = lane & 3;    // 0..3
    const int wm = wid >> 2;     // 0..1
    const int wn = wid & 3;      // 0..3

    const uint32_t s_rawA = smem_u32(sm + OFF_RAWA);
    const uint32_t s_rawB = smem_u32(sm + OFF_RAWB);

    auto fill = [&](int kc) {
        const size_t koff = (size_t)kc * BK;
        #pragma unroll
        for (int j = 0; j < 4; ++j) {
            const int ch = tid + 256 * j;        // 0..1023
            const int row = ch >> 3;
            const int c8 = (ch & 7) * 4;
            cp16(s_rawA + (row * 32 + c8) * 4, A + (size_t)(bm + row) * DIM + koff + c8);
            cp16(s_rawB + (row * 32 + c8) * 4, B + (size_t)(bn + row) * DIM + koff + c8);
        }
        asm volatile("cp.async.commit_group;" ::: "memory");
    };

    float acc[4][4][4];
    #pragma unroll
    for (int mf = 0; mf < 4; ++mf)
        #pragma unroll
        for (int nf = 0; nf < 4; ++nf)
            #pragma unroll
            for (int e = 0; e < 4; ++e) acc[mf][nf][e] = 0.f;

    fill(0);
    asm volatile("cp.async.wait_group 0;" ::: "memory");
    __syncthreads();

    uint32_t* abh = (uint32_t*)(sm + OFF_ABH);
    uint32_t* alb = (uint32_t*)(sm + OFF_ALB);
    uint32_t* bbh = (uint32_t*)(sm + OFF_BBH);
    uint32_t* blb = (uint32_t*)(sm + OFF_BLB);

    for (int s = 0; s < NSTAGE; ++s) {
        // ---- split pass: raw fp32 -> packed bf16 hi/lo planes ----
        #pragma unroll
        for (int j = 0; j < 4; ++j) {
            const int f = tid + 256 * j;    // float4 id 0..1023
            const int row = f >> 3;
            const int c4 = (f & 7) * 4;
            const int pidx = row * HSTRIDE + (f & 7) * 2;
            float4 va = *(const float4*)(sm + OFF_RAWA + row * 32 + c4);
            float4 vb = *(const float4*)(sm + OFF_RAWB + row * 32 + c4);
            uint32_t h0 = bfpack(va.x, va.y);
            uint32_t h1 = bfpack(va.z, va.w);
            float l0 = va.x - __uint_as_float(h0 << 16);
            float l1 = va.y - __uint_as_float(h0 & 0xFFFF0000u);
            float l2 = va.z - __uint_as_float(h1 << 16);
            float l3 = va.w - __uint_as_float(h1 & 0xFFFF0000u);
            *(uint2*)(abh + pidx) = make_uint2(h0, h1);
            *(uint2*)(alb + pidx) = make_uint2(bfpack(l0, l1), bfpack(l2, l3));
            h0 = bfpack(vb.x, vb.y);
            h1 = bfpack(vb.z, vb.w);
            l0 = vb.x - __uint_as_float(h0 << 16);
            l1 = vb.y - __uint_as_float(h0 & 0xFFFF0000u);
            l2 = vb.z - __uint_as_float(h1 << 16);
            l3 = vb.w - __uint_as_float(h1 & 0xFFFF0000u);
            *(uint2*)(bbh + pidx) = make_uint2(h0, h1);
            *(uint2*)(blb + pidx) = make_uint2(bfpack(l0, l1), bfpack(l2, l3));
        }
        __syncthreads();   // planes ready; raw buffer free

        // issue next stage's loads now — they overlap the MMA phase below
        if (s + 1 < NSTAGE) fill(s + 1);

        // ---- 3-term bf16 MMA: 2 slabs of k16 ----
        #pragma unroll
        for (int slab = 0; slab < 2; ++slab) {
            const int pb = slab * 8 + tig;
            uint32_t Bhf[4][2], Blf[4][2];
            #pragma unroll
            for (int nf = 0; nf < 4; ++nf) {
                const int r = (wn * 32 + nf * 8 + gid) * HSTRIDE;
                Bhf[nf][0] = bbh[r + pb]; Bhf[nf][1] = bbh[r + pb + 4];
                Blf[nf][0] = blb[r + pb]; Blf[nf][1] = blb[r + pb + 4];
            }
            #pragma unroll
            for (int mf = 0; mf < 4; ++mf) {
                const int r0 = (wm * 64 + mf * 16 + gid) * HSTRIDE;
                const int r1 = r0 + 8 * HSTRIDE;
                uint32_t h0 = abh[r0 + pb], h1 = abh[r1 + pb];
                uint32_t h2 = abh[r0 + pb + 4], h3 = abh[r1 + pb + 4];
                uint32_t l0 = alb[r0 + pb], l1 = alb[r1 + pb];
                uint32_t l2 = alb[r0 + pb + 4], l3 = alb[r1 + pb + 4];
                #pragma unroll
                for (int nf = 0; nf < 4; ++nf)   // hi*hi
                    mma_bf16(acc[mf][nf], h0, h1, h2, h3, Bhf[nf][0], Bhf[nf][1]);
                #pragma unroll
                for (int nf = 0; nf < 4; ++nf)   // hi*lo
                    mma_bf16(acc[mf][nf], h0, h1, h2, h3, Blf[nf][0], Blf[nf][1]);
                #pragma unroll
                for (int nf = 0; nf < 4; ++nf)   // lo*hi
                    mma_bf16(acc[mf][nf], l0, l1, l2, l3, Bhf[nf][0], Bhf[nf][1]);
            }
        }

        if (s + 1 < NSTAGE) asm volatile("cp.async.wait_group 0;" ::: "memory");
        __syncthreads();   // raw(s+1) ready; planes free for next split
    }

    // ---------------- epilogue ----------------
    #pragma unroll
    for (int mf = 0; mf < 4; ++mf) {
        #pragma unroll
        for (int nf = 0; nf < 4; ++nf) {
            float* cr = acc[mf][nf];
            const int r0 = bm + wm * 64 + mf * 16 + gid;
            const int r1 = r0 + 8;
            const int cb = bn + wn * 32 + nf * 8 + 2 * tig;
            if (MODE == 1) {
                cr[0] = fmaf(cr[0], -0.5f, (cb == r0)     ? 1.5f : 0.0f);
                cr[1] = fmaf(cr[1], -0.5f, (cb + 1 == r0) ? 1.5f : 0.0f);
                cr[2] = fmaf(cr[2], -0.5f, (cb == r1)     ? 1.5f : 0.0f);
                cr[3] = fmaf(cr[3], -0.5f, (cb + 1 == r1) ? 1.5f : 0.0f);
            }
            *(float2*)(C + (size_t)r0 * DIM + cb) = make_float2(cr[0], cr[1]);
            *(float2*)(C + (size_t)r1 * DIM + cb) = make_float2(cr[2], cr[3]);
            if (ti != tj) {  // mirror transposed
                C[(size_t)cb * DIM + r0]       = cr[0];
                C[(size_t)(cb + 1) * DIM + r0] = cr[1];
                C[(size_t)cb * DIM + r1]       = cr[2];
                C[(size_t)(cb + 1) * DIM + r1] = cr[3];
            }
        }
    }
}

template <int MODE>
__global__ void __launch_bounds__(256, 2) gemm_tc(const float* __restrict__ Ag,
                                                  const float* __restrict__ Bg,
                                                  float* __restrict__ Cg) {
    extern __shared__ float sm[];
    const size_t off = (size_t)blockIdx.z * MAT;
    gemm_body<MODE>(Ag + off, Bg + off, Cg + off,
                    c_ti[blockIdx.x], c_tj[blockIdx.x], sm);
}

// merged launch: y==0 -> C0 = A0@B0 ; y==1 -> C1 = A1@B1 (both MODE 0)
__global__ void __launch_bounds__(256, 2) gemm_dual(
    const float* __restrict__ A0, const float* __restrict__ B0, float* __restrict__ C0,
    const float* __restrict__ A1, const float* __restrict__ B1, float* __restrict__ C1) {
    extern __shared__ float sm[];
    const size_t off = (size_t)blockIdx.z * MAT;
    if (blockIdx.y == 0)
        gemm_body<0>(A0 + off, B0 + off, C0 + off, c_ti[blockIdx.x], c_tj[blockIdx.x], sm);
    else
        gemm_body<0>(A1 + off, B1 + off, C1 + off, c_ti[blockIdx.x], c_tj[blockIdx.x], sm);
}

// ---------------- host launcher ----------------
extern "C" void kernel_launch(void* const* d_in, const int* in_sizes, int n_in,
                              void* d_out, int out_size) {
    const float* x = (const float*)d_in[0];
    float* out = (float*)d_out;

    float *Yb, *Zb, *Tb;
    cudaGetSymbolAddress((void**)&Yb, g_Y);
    cudaGetSymbolAddress((void**)&Zb, g_Z);
    cudaGetSymbolAddress((void**)&Tb, g_T);
    const size_t half = (size_t)BATCH * MAT;
    float* Y[2] = {Yb, Yb + half};
    float* Z[2] = {Zb, Zb + half};

    cudaFuncSetAttribute(gemm_tc<0>, cudaFuncAttributeMaxDynamicSharedMemorySize, SMEM_BYTES);
    cudaFuncSetAttribute(gemm_tc<1>, cudaFuncAttributeMaxDynamicSharedMemorySize, SMEM_BYTES);
    cudaFuncSetAttribute(gemm_dual, cudaFuncAttributeMaxDynamicSharedMemorySize, SMEM_BYTES);

    norm_kernel<<<BATCH, 256>>>(x);
    const int total4 = BATCH * MAT / 4;
    init_kernel<<<(total4 + 255) / 256, 256>>>(x, Y[0]);

    // iter 0 (Z0 = I): T0 = 1.5I - 0.5*Y0 stored as Z[0]; Y1 = Y0 @ T0
    zt_kernel<<<(total4 + 255) / 256, 256>>>(Y[0], Z[0]);

    dim3 ggrid(10, 1, BATCH);
    dim3 dgrid(10, 2, BATCH);
    gemm_tc<0><<<ggrid, 256, SMEM_BYTES>>>(Y[0], Z[0], Y[1]);
    int ycur = 1, zcur = 0;

    for (int it = 1; it < NUM_ITER; ++it) {
        // T = 1.5 I - 0.5 * Z @ Y
        gemm_tc<1><<<ggrid, 256, SMEM_BYTES>>>(Z[zcur], Y[ycur], Tb);
        if (it < NUM_ITER - 1) {
            // merged: Y' = Y @ T and Z' = T @ Z
            gemm_dual<<<dgrid, 256, SMEM_BYTES>>>(Y[ycur], Tb, Y[1 - ycur],
                                                  Tb, Z[zcur], Z[1 - zcur]);
            ycur ^= 1; zcur ^= 1;
        } else {
            gemm_tc<0><<<ggrid, 256, SMEM_BYTES>>>(Y[ycur], Tb, Y[1 - ycur]);
            ycur ^= 1;
        }
    }

    final_kernel<<<(total4 + 255) / 256, 256>>>(Y[ycur], out);
}